// round 17
// baseline (speedup 1.0000x reference)
#include <cuda_runtime.h>
#include <math.h>
#include <stdint.h>

// AfmoeTokenChoiceRouter — FFMA2 scalar GEMM (fp32-exact) + fp64 boundary refinement
// logits = x[T,H] @ W^T (T=16384, H=2048, E=64); sigmoid; biased top-8; norm; *2.5
// Output: [ top_scores (T*8 f32) | selected_experts as f32 (T*8) ]
// R17: mma.sync measured hard-capped at ~13 cyc/HMMA/SM on sm_103 (3 kernels agree
//      within 3%) -> floor 307us. FMA pipe does 128 FMA/cyc/SM with f32x2 -> ~73us
//      floor. Scalar tile 4tok x 8exp, 2 CTAs/SM, double-buffered smem, 1 bar/chunk.

#define TOKS   64
#define TPB    128
#define TOPK   8
#define ROUTE_SCALE 2.5f
#define TAU    5e-5f

#define RS     68                    // smem row stride in floats (272B, 16B-aligned)
#define A_SZ   (32 * RS)             // 2176 floats per buffer half
#define BUFW   (2 * A_SZ)            // 4352 floats (A + B)
#define DYN_BYTES (2 * BUFW * 4)     // 34816 B (double buffer; Sc aliases buf0)

typedef unsigned long long ull;

static __device__ __forceinline__ ull pack2(float lo, float hi){
    ull r; asm("mov.b64 %0, {%1, %2};" : "=l"(r) : "f"(lo), "f"(hi)); return r;
}
static __device__ __forceinline__ void unpack2(float& lo, float& hi, ull v){
    asm("mov.b64 {%0, %1}, %2;" : "=f"(lo), "=f"(hi) : "l"(v));
}
static __device__ __forceinline__ void fma2(ull& d, ull a, ull b){
    asm("fma.rn.f32x2 %0, %1, %2, %3;" : "=l"(d) : "l"(a), "l"(b), "l"(d));
}

__global__ __launch_bounds__(TPB)
void router_main(const float* __restrict__ x, const float* __restrict__ bias,
                 const float* __restrict__ w, float* __restrict__ out, int T, int H)
{
    extern __shared__ __align__(16) float dyn[];
    __shared__ float Sb[64];

    const int tid  = threadIdx.x;
    const int warp = tid >> 5;
    const int lane = tid & 31;
    const int ty   = tid & 15;        // token group: toks 4*ty..4*ty+3
    const int ey   = tid >> 4;        // expert group: exps 8*ey..8*ey+7
    const int tok0 = blockIdx.x * TOKS;
    const int nchunk = H >> 5;

    if (tid < 64) Sb[tid] = bias[tid];

    // staging: thread covers row st (token AND expert index 0..63), k-half skh
    const int st  = tid >> 1;
    const int skh = tid & 1;
    const float* xs = x + (size_t)(tok0 + st) * H + skh * 16;
    const float* ws = w + (size_t)st * H + skh * 16;

    ull acc[4][4];                    // [tok][exp-pair] f32x2
    #pragma unroll
    for (int t = 0; t < 4; t++)
        #pragma unroll
        for (int e = 0; e < 4; e++) acc[t][e] = 0ULL;

    float4 ra[4], rb[4];
    #pragma unroll
    for (int j = 0; j < 4; j++){
        ra[j] = *(const float4*)(xs + j * 4);
        rb[j] = *(const float4*)(ws + j * 4);
    }

    for (int kb = 0; kb < nchunk; kb++){
        float* As = dyn + (kb & 1) * BUFW;
        float* Bs = As + A_SZ;

        // ---- store staged chunk (16 STS.32 each for A and B, 2-way conflicts) ----
        #pragma unroll
        for (int j = 0; j < 4; j++){
            const int kk = skh * 16 + j * 4;
            As[(kk    ) * RS + st] = ra[j].x;  As[(kk + 1) * RS + st] = ra[j].y;
            As[(kk + 2) * RS + st] = ra[j].z;  As[(kk + 3) * RS + st] = ra[j].w;
            Bs[(kk    ) * RS + st] = rb[j].x;  Bs[(kk + 1) * RS + st] = rb[j].y;
            Bs[(kk + 2) * RS + st] = rb[j].z;  Bs[(kk + 3) * RS + st] = rb[j].w;
        }
        __syncthreads();

        // ---- prefetch next chunk (in flight during inner loop) ----
        if (kb + 1 < nchunk){
            const float* xp = xs + (size_t)(kb + 1) * 32;
            const float* wp = ws + (size_t)(kb + 1) * 32;
            #pragma unroll
            for (int j = 0; j < 4; j++){
                ra[j] = *(const float4*)(xp + j * 4);
                rb[j] = *(const float4*)(wp + j * 4);
            }
        }

        // ---- inner: 32 k-steps, 16 independent FFMA2 each ----
        #pragma unroll 8
        for (int k = 0; k < 32; k++){
            const float* rowA = As + k * RS;
            const float* rowB = Bs + k * RS;
            float4 av = *(const float4*)(rowA + 4 * ty);
            float4 b0 = *(const float4*)(rowB + 8 * ey);
            float4 b1 = *(const float4*)(rowB + 8 * ey + 4);
            ull a0 = pack2(av.x, av.x), a1 = pack2(av.y, av.y);
            ull a2 = pack2(av.z, av.z), a3 = pack2(av.w, av.w);
            ull p0 = pack2(b0.x, b0.y), p1 = pack2(b0.z, b0.w);
            ull p2 = pack2(b1.x, b1.y), p3 = pack2(b1.z, b1.w);
            fma2(acc[0][0], a0, p0); fma2(acc[0][1], a0, p1);
            fma2(acc[0][2], a0, p2); fma2(acc[0][3], a0, p3);
            fma2(acc[1][0], a1, p0); fma2(acc[1][1], a1, p1);
            fma2(acc[1][2], a1, p2); fma2(acc[1][3], a1, p3);
            fma2(acc[2][0], a2, p0); fma2(acc[2][1], a2, p1);
            fma2(acc[2][2], a2, p2); fma2(acc[2][3], a2, p3);
            fma2(acc[3][0], a3, p0); fma2(acc[3][1], a3, p1);
            fma2(acc[3][2], a3, p2); fma2(acc[3][3], a3, p3);
        }
        __syncthreads();
    }

    // ---- epilogue: sigmoid -> Sc[64][66] (aliases buffer 0; disjoint from buf1) ----
    float* Sc = dyn;
    #pragma unroll
    for (int t = 0; t < 4; t++)
        #pragma unroll
        for (int e = 0; e < 4; e++){
            float lo, hi;
            unpack2(lo, hi, acc[t][e]);
            Sc[(4 * ty + t) * 66 + 8 * ey + 2 * e]     = 1.0f / (1.0f + expf(-lo));
            Sc[(4 * ty + t) * 66 + 8 * ey + 2 * e + 1] = 1.0f / (1.0f + expf(-hi));
        }
    __syncthreads();

    // ---- top-10 selection + exact fp64 refinement (proven R10/R14/R16 logic) ----
    const unsigned FULL = 0xFFFFFFFFu;
    for (int t = 0; t < 16; t++){
        const int tl = warp * 16 + t;
        const int gt = tok0 + tl;
        const int e0 = lane, e1 = lane + 32;
        float b0v = Sc[tl * 66 + e0] + Sb[e0];
        float b1v = Sc[tl * 66 + e1] + Sb[e1];

        float myval = 0.0f, mybv = -1e30f;
        int   myidx = 0;
        float ssum  = 0.0f;

        #pragma unroll
        for (int i = 0; i < 10; i++){
            float v; int idx;
            if (b0v >= b1v) { v = b0v; idx = e0; }
            else            { v = b1v; idx = e1; }
            #pragma unroll
            for (int off = 16; off > 0; off >>= 1){
                float ov  = __shfl_xor_sync(FULL, v, off);
                int   oid = __shfl_xor_sync(FULL, idx, off);
                if (ov > v || (ov == v && oid < idx)) { v = ov; idx = oid; }
            }
            float sc = Sc[tl * 66 + idx];
            if (i < TOPK) ssum += sc;
            if (lane == i) { myval = sc; myidx = idx; mybv = v; }
            if (idx == e0) b0v = -INFINITY;
            if (idx == e1) b1v = -INFINITY;
        }

        float nxt = __shfl_down_sync(FULL, mybv, 1);
        bool close = (lane < 8) && (mybv - nxt < TAU);
        bool risky = __any_sync(FULL, close);

        if (!risky){
            const float scale = ROUTE_SCALE / (ssum + 1e-20f);
            if (lane < TOPK && gt < T){
                out[(size_t)gt * TOPK + lane]                    = myval * scale;
                out[(size_t)T * TOPK + (size_t)gt * TOPK + lane] = (float)myidx;
            }
        } else {
            const float* xr = x + (size_t)gt * H;
            double sc_d = 0.0, bd = -1e300;
            #pragma unroll 1
            for (int j = 0; j < 10; j++){
                int e = __shfl_sync(FULL, myidx, j);
                const float* wr = w + (size_t)e * H;
                double s = 0.0;
                #pragma unroll 4
                for (int m = 0; m < 16; m++){
                    int k = (m * 32 + lane) * 4;
                    float4 xv = *(const float4*)(xr + k);
                    float4 wv = *(const float4*)(wr + k);
                    s += (double)xv.x * wv.x + (double)xv.y * wv.y
                       + (double)xv.z * wv.z + (double)xv.w * wv.w;
                }
                #pragma unroll
                for (int off = 16; off > 0; off >>= 1)
                    s += __shfl_xor_sync(FULL, s, off);
                if (lane == j){
                    double sig = 1.0 / (1.0 + exp(-s));
                    sc_d = sig;
                    bd   = sig + (double)Sb[myidx];
                }
            }
            double rb2 = (lane < 10) ? bd : -1e300;
            int    ri  = (lane < 10) ? myidx : (1 << 30);
            int rank = 0;
            #pragma unroll 1
            for (int l = 0; l < 10; l++){
                double ob = __shfl_sync(FULL, rb2, l);
                int    oi = __shfl_sync(FULL, ri, l);
                if (ob > rb2 || (ob == rb2 && oi < ri)) rank++;
            }
            double contrib = (lane < 10 && rank < TOPK) ? sc_d : 0.0;
            #pragma unroll
            for (int off = 16; off > 0; off >>= 1)
                contrib += __shfl_xor_sync(FULL, contrib, off);
            const float scale = ROUTE_SCALE / ((float)contrib + 1e-20f);
            if (lane < 10 && rank < TOPK && gt < T){
                out[(size_t)gt * TOPK + rank]                    = (float)sc_d * scale;
                out[(size_t)T * TOPK + (size_t)gt * TOPK + rank] = (float)myidx;
            }
        }
    }
}

extern "C" void kernel_launch(void* const* d_in, const int* in_sizes, int n_in,
                              void* d_out, int out_size)
{
    const float* x    = (const float*)d_in[0];
    const float* bias = (const float*)d_in[1];
    const float* w    = (const float*)d_in[2];

    const int E = in_sizes[1];                   // 64
    const int H = in_sizes[2] / E;               // 2048
    const int T = in_sizes[0] / H;               // 16384

    router_main<<<T / TOKS, TPB, DYN_BYTES>>>(x, bias, w, (float*)d_out, T, H);
}